// round 15
// baseline (speedup 1.0000x reference)
#include <cuda_runtime.h>
#include <cuda_bf16.h>
#include <cstdint>
#include <math.h>

constexpr int kH = 2048, kI = 1024, kE = 16, kTopK = 8, kR = 602, kT = 8192;
constexpr int kRP = 640;

// ---------------- device scratch ----------------
__device__ __align__(16) unsigned short d_xs_hi[kT * kH];
__device__ __align__(16) unsigned short d_xs_lo[kT * kH];
__device__ __align__(16) unsigned short d_wgu_hi[2 * kI * kH];
__device__ __align__(16) unsigned short d_wgu_lo[2 * kI * kH];
__device__ __align__(16) unsigned short d_wd_hi[kH * kI];
__device__ __align__(16) unsigned short d_wd_lo[kH * kI];
__device__ __align__(16) unsigned short d_ag_hi[kE * kR * kH];
__device__ __align__(16) unsigned short d_ag_lo[kE * kR * kH];
__device__ __align__(16) unsigned short d_au_hi[kE * kR * kH];
__device__ __align__(16) unsigned short d_au_lo[kE * kR * kH];
__device__ __align__(16) unsigned short d_bg_hi[kE * kI * kRP];
__device__ __align__(16) unsigned short d_bg_lo[kE * kI * kRP];
__device__ __align__(16) unsigned short d_bu_hi[kE * kI * kRP];
__device__ __align__(16) unsigned short d_bu_lo[kE * kI * kRP];
__device__ __align__(16) unsigned short d_ad_hi[kE * kR * kI];
__device__ __align__(16) unsigned short d_ad_lo[kE * kR * kI];
__device__ __align__(16) unsigned short d_bd_hi[kE * kH * kRP];
__device__ __align__(16) unsigned short d_bd_lo[kE * kH * kRP];
__device__ __align__(16) unsigned short d_tgu_hi[kE * kT * 2 * kRP];
__device__ __align__(16) unsigned short d_tgu_lo[kE * kT * 2 * kRP];
__device__ __align__(16) unsigned short d_td_hi[kE * kT * kRP];
__device__ __align__(16) unsigned short d_td_lo[kE * kT * kRP];
__device__ __align__(16) unsigned short d_h_hi[kE * kT * kI];
__device__ __align__(16) unsigned short d_h_lo[kE * kT * kI];
__device__ __align__(16) unsigned short d_hb_hi[kT * kI];
__device__ __align__(16) unsigned short d_hb_lo[kT * kI];
__device__ float g_base_gu[2 * kT * kI];
__device__ float g_hbar[kT * kI];
__device__ float g_combine[kT * kE];
__device__ int   g_lists[kE * kT];
__device__ int   g_counts[kE];

// ---------------- helpers ----------------
__device__ __forceinline__ uint32_t smem_u32(const void* p) {
    uint32_t a;
    asm("{ .reg .u64 t; cvta.to.shared.u64 t, %1; cvt.u32.u64 %0, t; }"
        : "=r"(a) : "l"(p));
    return a;
}
__device__ __forceinline__ void split_bf16(float v, unsigned short& h, unsigned short& l) {
    __nv_bfloat16 bh = __float2bfloat16(v);
    float r = v - __bfloat162float(bh);
    __nv_bfloat16 bl = __float2bfloat16(r);
    h = __bfloat16_as_ushort(bh);
    l = __bfloat16_as_ushort(bl);
}
__device__ __forceinline__ void red_v2(float* ptr, float a, float b) {
    asm volatile("red.global.add.v2.f32 [%0], {%1, %2};"
                 :: "l"(ptr), "f"(a), "f"(b) : "memory");
}

#define LDM4(r, a)                                                            \
    asm volatile("ldmatrix.sync.aligned.m8n8.x4.shared.b16 {%0,%1,%2,%3}, [%4];" \
                 : "=r"((r)[0]), "=r"((r)[1]), "=r"((r)[2]), "=r"((r)[3])     \
                 : "r"(a))

#define MMA(c, a, b0, b1)                                                     \
    asm volatile("mma.sync.aligned.m16n8k16.row.col.f32.bf16.bf16.f32 "       \
                 "{%0,%1,%2,%3},{%4,%5,%6,%7},{%8,%9},{%0,%1,%2,%3};"         \
                 : "+f"((c)[0]), "+f"((c)[1]), "+f"((c)[2]), "+f"((c)[3])     \
                 : "r"((a)[0]), "r"((a)[1]), "r"((a)[2]), "r"((a)[3]),        \
                   "r"(b0), "r"(b1))

#define MMA6(accA, accB, ah, al, bh, bl)                                      \
    do {                                                                      \
        MMA(accA, ah, (bh)[0], (bh)[2]);                                      \
        MMA(accB, ah, (bh)[1], (bh)[3]);                                      \
        MMA(accA, ah, (bl)[0], (bl)[2]);                                      \
        MMA(accB, ah, (bl)[1], (bl)[3]);                                      \
        MMA(accA, al, (bh)[0], (bh)[2]);                                      \
        MMA(accB, al, (bh)[1], (bh)[3]);                                      \
    } while (0)

__device__ __forceinline__ void cpa16(uint32_t dst, const void* src, int sz) {
    asm volatile("cp.async.cg.shared.global [%0], [%1], 16, %2;"
                 :: "r"(dst), "l"(src), "r"(sz));
}

__device__ __forceinline__ uint32_t swz(int row, int chunk) {
    return (uint32_t)(row * 64 + ((chunk ^ ((row >> 1) & 3)) << 4));
}

// ---------------- init ----------------
__global__ void init_kernel(float* __restrict__ hbar) {
    long idx = (long)blockIdx.x * blockDim.x + threadIdx.x;
    long stride = (long)gridDim.x * blockDim.x;
    long totalH = (long)(kT * kI) / 4;
    float4 z = make_float4(0.f, 0.f, 0.f, 0.f);
    float4* h4 = (float4*)hbar;
    for (long i = idx; i < totalH; i += stride) h4[i] = z;
    if (idx < kE) g_counts[idx] = 0;
}

// ---------------- router ----------------
__global__ void router_kernel(const float* __restrict__ x,
                              const float* __restrict__ wr,
                              float* __restrict__ logits_out) {
    int t = blockIdx.x;
    __shared__ float xs[kH];
    __shared__ float lg[kE];
    int tid = threadIdx.x;
    for (int i = tid; i < kH; i += 256) xs[i] = x[(long)t * kH + i];
    __syncthreads();
    int w = tid >> 5, lane = tid & 31;
    #pragma unroll
    for (int eo = 0; eo < 2; eo++) {
        int e = w * 2 + eo;
        const float* wre = wr + (long)e * kH;
        float s = 0.0f;
        for (int i = lane; i < kH; i += 32) s += xs[i] * wre[i];
        #pragma unroll
        for (int o = 16; o; o >>= 1) s += __shfl_xor_sync(0xffffffff, s, o);
        if (lane == 0) lg[e] = s;
    }
    __syncthreads();
    if (tid == 0) {
        float mx = lg[0];
        for (int e = 1; e < kE; e++) mx = fmaxf(mx, lg[e]);
        float p[kE]; float sum = 0.0f;
        for (int e = 0; e < kE; e++) { p[e] = expf(lg[e] - mx); sum += p[e]; }
        float inv = 1.0f / sum;
        for (int e = 0; e < kE; e++) p[e] *= inv;
        bool used[kE];
        for (int e = 0; e < kE; e++) used[e] = false;
        int sel[kTopK]; float tsum = 0.0f;
        for (int k = 0; k < kTopK; k++) {
            int bi = -1; float bv = -1.0f;
            for (int e = 0; e < kE; e++)
                if (!used[e] && p[e] > bv) { bv = p[e]; bi = e; }
            used[bi] = true; sel[k] = bi; tsum += bv;
        }
        float itn = 1.0f / tsum;
        for (int e = 0; e < kE; e++)
            g_combine[t * kE + e] = used[e] ? p[e] * itn : 0.0f;
        for (int k = 0; k < kTopK; k++) {
            int e = sel[k];
            int pos = atomicAdd(&g_counts[e], 1);
            g_lists[e * kT + pos] = t;
        }
    }
    if (tid < kE) logits_out[t * kE + tid] = lg[tid];
}

// ---------------- vectorized split ----------------
__global__ void splitv_kernel(const float* __restrict__ src, int srcLd,
                              unsigned short* __restrict__ hi,
                              unsigned short* __restrict__ lo, int dstLd) {
    long row = blockIdx.y;
    int col = (blockIdx.x * 256 + threadIdx.x) * 8;
    if (col >= dstLd) return;
    const float* s = src + row * srcLd;
    unsigned short h[8], l[8];
    #pragma unroll
    for (int j = 0; j < 8; ++j) {
        float v = (col + j < srcLd) ? __ldg(s + col + j) : 0.0f;
        split_bf16(v, h[j], l[j]);
    }
    long o = row * dstLd + col;
    *(uint4*)(hi + o) = *(const uint4*)h;
    *(uint4*)(lo + o) = *(const uint4*)l;
}

// ---------------- generic GEMM ----------------
struct GArgs {
    const unsigned short *A1h, *A1l; int lda1;
    const unsigned short *Bh, *Bl;   int ldb;  int nBv;
    const unsigned short *Bn2h, *Bn2l; int nSplit; int nBn2v;
    int K;
    float* C; int ldc;
    int M_static; const int* countBase; const int* listBase; int gatherA;
    const float* combine;
    unsigned short *Ch, *Cl;
    int mode;
    int useW;
    long eStrideA1, eStrideB, eStrideBn2;
    long eStrideC;
};

constexpr int STAGE_B = 32768;
constexpr int PL = 8192;
constexpr int GSMEM = 3072 + 3 * STAGE_B;  // 101376

// modes: 0: C=acc ; 2: red.v2(C[tok], acc) ; 3: split->Ch/Cl (×w if useW) ; 5: C[r]+=acc
template <int MODE>
__global__ __launch_bounds__(256, 2) void gemm_mma(GArgs g) {
    int ez = blockIdx.z;
    int M = g.countBase ? g.countBase[ez] : g.M_static;
    int row0 = blockIdx.y * 128;
    if (row0 >= M) return;
    int col0 = blockIdx.x * 128;

    const unsigned short* A1h = g.A1h + (long)ez * g.eStrideA1;
    const unsigned short* A1l = g.A1l + (long)ez * g.eStrideA1;
    const unsigned short* Bh  = g.Bh + (long)ez * g.eStrideB;
    const unsigned short* Bl  = g.Bl + (long)ez * g.eStrideB;
    float* C = g.C ? g.C + (long)ez * g.eStrideC : nullptr;
    unsigned short* Ch = g.Ch ? g.Ch + (long)ez * g.eStrideC : nullptr;
    unsigned short* Cl = g.Cl ? g.Cl + (long)ez * g.eStrideC : nullptr;
    const int* list = g.listBase ? g.listBase + (long)ez * kT : nullptr;

    extern __shared__ char sm[];
    int*   arow = (int*)sm;
    int*   tokS = (int*)(sm + 1024);
    float* wS   = (float*)(sm + 2048);
    uint32_t stages_u = smem_u32(sm + 3072);

    int tid = threadIdx.x;
    int lane = tid & 31, wid = tid >> 5;
    int wm = wid & 3, wn = wid >> 2;

    if (tid < 128) {
        int i = tid;
        int r = row0 + i;
        int rr = (r < M) ? r : (M - 1);
        int tk = list ? list[rr] : rr;
        tokS[i] = tk;
        arow[i] = g.gatherA ? tk : rr;
        wS[i] = (MODE == 3 && g.useW) ? g.combine[tk * kE + ez] : 1.0f;
    }
    __syncthreads();

    int c8 = tid & 3;
    int rA0 = tid >> 2, rA1 = (tid + 256) >> 2;
    const unsigned short* aH0 = A1h + (long)arow[rA0] * g.lda1 + c8 * 8;
    const unsigned short* aL0 = A1l + (long)arow[rA0] * g.lda1 + c8 * 8;
    const unsigned short* aH1 = A1h + (long)arow[rA1] * g.lda1 + c8 * 8;
    const unsigned short* aL1 = A1l + (long)arow[rA1] * g.lda1 + c8 * 8;
    uint32_t aD0 = swz(rA0, c8), aD1 = swz(rA1, c8);

    const unsigned short *bH0, *bL0, *bH1, *bL1;
    int v0, v1;
    {
        int gn = col0 + rA0;
        int rr; const unsigned short *ph, *pl;
        if (gn >= g.nSplit) { ph = g.Bn2h + (long)ez * g.eStrideBn2; pl = g.Bn2l + (long)ez * g.eStrideBn2; rr = gn - g.nSplit; v0 = (rr < g.nBn2v) ? 16 : 0; }
        else                { ph = Bh; pl = Bl; rr = gn; v0 = (gn < g.nBv) ? 16 : 0; }
        if (!v0) rr = 0;
        bH0 = ph + (long)rr * g.ldb + c8 * 8;
        bL0 = pl + (long)rr * g.ldb + c8 * 8;
        gn = col0 + rA1;
        if (gn >= g.nSplit) { ph = g.Bn2h + (long)ez * g.eStrideBn2; pl = g.Bn2l + (long)ez * g.eStrideBn2; rr = gn - g.nSplit; v1 = (rr < g.nBn2v) ? 16 : 0; }
        else                { ph = Bh; pl = Bl; rr = gn; v1 = (gn < g.nBv) ? 16 : 0; }
        if (!v1) rr = 0;
        bH1 = ph + (long)rr * g.ldb + c8 * 8;
        bL1 = pl + (long)rr * g.ldb + c8 * 8;
    }
    uint32_t bD0 = swz(rA0, c8), bD1 = swz(rA1, c8);

    uint32_t aAddr[2][2], bAddr[4][2];
    {
        int ch0 = lane >> 4;
        #pragma unroll
        for (int mf = 0; mf < 2; ++mf) {
            int row = wm * 32 + mf * 16 + (lane & 15);
            #pragma unroll
            for (int k16 = 0; k16 < 2; ++k16)
                aAddr[mf][k16] = swz(row, ch0 + k16 * 2);
        }
        #pragma unroll
        for (int n16 = 0; n16 < 4; ++n16) {
            int row = wn * 64 + n16 * 16 + (lane & 15);
            #pragma unroll
            for (int k16 = 0; k16 < 2; ++k16)
                bAddr[n16][k16] = swz(row, ch0 + k16 * 2);
        }
    }

    float acc[2][8][4];
    #pragma unroll
    for (int a = 0; a < 2; a++)
        #pragma unroll
        for (int b = 0; b < 8; b++)
            #pragma unroll
            for (int c = 0; c < 4; c++) acc[a][b][c] = 0.0f;

    int nk = g.K >> 5;

    auto load_tile = [&](int stg) {
        uint32_t st = stages_u + stg * STAGE_B;
        cpa16(st + aD0, aH0, 16);
        cpa16(st + PL + aD0, aL0, 16);
        cpa16(st + aD1, aH1, 16);
        cpa16(st + PL + aD1, aL1, 16);
        cpa16(st + 2 * PL + bD0, bH0, v0);
        cpa16(st + 3 * PL + bD0, bL0, v0);
        cpa16(st + 2 * PL + bD1, bH1, v1);
        cpa16(st + 3 * PL + bD1, bL1, v1);
        asm volatile("cp.async.commit_group;");
        aH0 += 32; aL0 += 32; aH1 += 32; aL1 += 32;
        bH0 += 32; bL0 += 32; bH1 += 32; bL1 += 32;
    };

    load_tile(0);
    load_tile(1);
    int cmp = 0, ld = 2;
    for (int k = 0; k < nk; ++k) {
        if (k == nk - 1) asm volatile("cp.async.wait_group 0;");
        else             asm volatile("cp.async.wait_group 1;");
        __syncthreads();
        uint32_t sb = stages_u + cmp * STAGE_B;
        #pragma unroll
        for (int k16 = 0; k16 < 2; ++k16) {
            uint32_t ah[2][4], al[2][4];
            #pragma unroll
            for (int mf = 0; mf < 2; ++mf) {
                LDM4(ah[mf], sb + aAddr[mf][k16]);
                LDM4(al[mf], sb + PL + aAddr[mf][k16]);
            }
            #pragma unroll
            for (int n16 = 0; n16 < 4; ++n16) {
                uint32_t bh[4], bl[4];
                LDM4(bh, sb + 2 * PL + bAddr[n16][k16]);
                LDM4(bl, sb + 3 * PL + bAddr[n16][k16]);
                #pragma unroll
                for (int mf = 0; mf < 2; ++mf)
                    MMA6(acc[mf][n16 * 2 + 0], acc[mf][n16 * 2 + 1],
                         ah[mf], al[mf], bh, bl);
            }
        }
        if (k + 2 < nk) {
            load_tile(ld);
            ld = (ld == 2) ? 0 : ld + 1;
        }
        cmp = (cmp == 2) ? 0 : cmp + 1;
    }

    int quad = lane >> 2, ql = lane & 3;
    #pragma unroll
    for (int mf = 0; mf < 2; ++mf) {
        #pragma unroll
        for (int h = 0; h < 2; ++h) {
            int li = wm * 32 + mf * 16 + quad + h * 8;
            int r = row0 + li;
            if (r >= M) continue;
            int tk = tokS[li];
            float w = wS[li];
            #pragma unroll
            for (int n8 = 0; n8 < 8; ++n8) {
                int cc = col0 + wn * 64 + n8 * 8 + ql * 2;
                float v0f = acc[mf][n8][h * 2 + 0];
                float v1f = acc[mf][n8][h * 2 + 1];
                if (MODE == 0) {
                    *(float2*)&C[(long)r * g.ldc + cc] = make_float2(v0f, v1f);
                } else if (MODE == 2) {
                    red_v2(&C[(long)tk * g.ldc + cc], v0f, v1f);
                } else if (MODE == 3) {
                    unsigned short h0, l0, h1, l1;
                    split_bf16(w * v0f, h0, l0);
                    split_bf16(w * v1f, h1, l1);
                    long o = (long)r * g.ldc + cc;
                    *(ushort2*)&Ch[o] = make_ushort2(h0, h1);
                    *(ushort2*)&Cl[o] = make_ushort2(l0, l1);
                } else {  // MODE 5
                    float2* o = (float2*)&C[(long)r * g.ldc + cc];
                    float2 cur = *o;
                    cur.x += v0f; cur.y += v1f;
                    *o = cur;
                }
            }
        }
    }
}

// ---------------- fused B+C kernel ----------------
// tile: 128 expert-rows x 64 I-cols, 8 warps (4m x 2n) of 32x32.
// pass0: g = base_g[tok] + tg@Bg^T -> sg = silu(g) in regs
// pass1: u = base_u[tok] + tu@Bu^T ; h = sg*u -> split to Hh/Hl, red hbar += w*h
struct BCArgs {
    const unsigned short *Ah, *Al;       // tgu planes, lda = 2*kRP, row = expert-list pos
    const unsigned short *Bgh, *Bgl;     // per-expert stride kI*kRP
    const unsigned short *Buh, *Bul;
    const float *baseG, *baseU;          // ld kI, row = token
    const float *combine;
    float *hbar;
    unsigned short *Hh, *Hl;             // expert stride kT*kI, row = expert-list pos
    const int *counts; const int *lists;
};

constexpr int BC_STAGE = 24576;   // A 8192*2 | B 4096*2
constexpr int BC_PB = 16384, BC_PBL = 20480;
constexpr int BC_SMEM = 3072 + 3 * BC_STAGE;  // 76800

__global__ __launch_bounds__(256, 2) void gemm_bc(BCArgs g) {
    int ez = blockIdx.z;
    int M = g.counts[ez];
    int row0 = blockIdx.y * 128;
    if (row0 >= M) return;
    int col0 = blockIdx.x * 64;
    const int LDA = 2 * kRP;

    const unsigned short* Ah = g.Ah + (long)ez * ((long)kT * LDA);
    const unsigned short* Al = g.Al + (long)ez * ((long)kT * LDA);
    const int* list = g.lists + (long)ez * kT;

    extern __shared__ char sm[];
    int*   arow = (int*)sm;               // expert-list position (clamped)
    int*   tokS = (int*)(sm + 1024);      // token id
    float* wS   = (float*)(sm + 2048);
    uint32_t stages_u = smem_u32(sm + 3072);

    int tid = threadIdx.x;
    int lane = tid & 31, wid = tid >> 5;
    int wm = wid & 3, wn = wid >> 2;

    if (tid < 128) {
        int r = row0 + tid;
        int rr = (r < M) ? r : (M - 1);
        arow[tid] = rr;
        int tk = list[rr];
        tokS[tid] = tk;
        wS[tid] = g.combine[tk * kE + ez];
    }
    __syncthreads();

    int c8 = tid & 3;
    int rA0 = tid >> 2, rA1 = (tid + 256) >> 2;
    uint32_t aD0 = swz(rA0, c8), aD1 = swz(rA1, c8);
    long aOff0 = (long)arow[rA0] * LDA + c8 * 8;   // FIXED: expert-list row, not token
    long aOff1 = (long)arow[rA1] * LDA + c8 * 8;
    int brow = tid >> 2;                  // 0..63
    uint32_t bD = swz(brow, c8);
    long bOff = (long)(col0 + brow) * kRP + c8 * 8;

    uint32_t aAddr[2][2], bAddr[2][2];
    {
        int ch0 = lane >> 4;
        #pragma unroll
        for (int mf = 0; mf < 2; ++mf) {
            int row = wm * 32 + mf * 16 + (lane & 15);
            #pragma unroll
            for (int k16 = 0; k16 < 2; ++k16)
                aAddr[mf][k16] = swz(row, ch0 + k16 * 2);
        }
        #pragma unroll
        for (int n16 = 0; n16 < 2; ++n16) {
            int row = wn * 32 + n16 * 16 + (lane & 15);
            #pragma unroll
            for (int k16 = 0; k16 < 2; ++k16)
                bAddr[n16][k16] = swz(row, ch0 + k16 * 2);
        }
    }

    float acc[2][4][4];
    float sg[2][4][4];
    const int nk = kRP >> 5;  // 20

    #pragma unroll
    for (int pass = 0; pass < 2; ++pass) {
        const unsigned short* aH0 = Ah + aOff0 + pass * kRP;
        const unsigned short* aL0 = Al + aOff0 + pass * kRP;
        const unsigned short* aH1 = Ah + aOff1 + pass * kRP;
        const unsigned short* aL1 = Al + aOff1 + pass * kRP;
        const unsigned short* bH = (pass ? g.Buh : g.Bgh) + (long)ez * kI * kRP + bOff;
        const unsigned short* bL = (pass ? g.Bul : g.Bgl) + (long)ez * kI * kRP + bOff;

        #pragma unroll
        for (int a = 0; a < 2; a++)
            #pragma unroll
            for (int b = 0; b < 4; b++)
                #pragma unroll
                for (int c = 0; c < 4; c++) acc[a][b][c] = 0.0f;

        auto load_tile = [&](int stg) {
            uint32_t st = stages_u + stg * BC_STAGE;
            cpa16(st + aD0, aH0, 16);
            cpa16(st + PL + aD0, aL0, 16);
            cpa16(st + aD1, aH1, 16);
            cpa16(st + PL + aD1, aL1, 16);
            cpa16(st + BC_PB + bD, bH, 16);
            cpa16(st + BC_PBL + bD, bL, 16);
            asm volatile("cp.async.commit_group;");
            aH0 += 32; aL0 += 32; aH1 += 32; aL1 += 32;
            bH += 32; bL += 32;
        };

        load_tile(0);
        load_tile(1);
        int cmp = 0, ld = 2;
        for (int k = 0; k < nk; ++k) {
            if (k == nk - 1) asm volatile("cp.async.wait_group 0;");
            else             asm volatile("cp.async.wait_group 1;");
            __syncthreads();
            uint32_t sb = stages_u + cmp * BC_STAGE;
            #pragma unroll
            for (int k16 = 0; k16 < 2; ++k16) {
                uint32_t ah[2][4], al[2][4];
                #pragma unroll
                for (int mf = 0; mf < 2; ++mf) {
                    LDM4(ah[mf], sb + aAddr[mf][k16]);
                    LDM4(al[mf], sb + PL + aAddr[mf][k16]);
                }
                #pragma unroll
                for (int n16 = 0; n16 < 2; ++n16) {
                    uint32_t bh[4], bl[4];
                    LDM4(bh, sb + BC_PB + bAddr[n16][k16]);
                    LDM4(bl, sb + BC_PBL + bAddr[n16][k16]);
                    #pragma unroll
                    for (int mf = 0; mf < 2; ++mf)
                        MMA6(acc[mf][n16 * 2 + 0], acc[mf][n16 * 2 + 1],
                             ah[mf], al[mf], bh, bl);
                }
            }
            if (k + 2 < nk) {
                load_tile(ld);
                ld = (ld == 2) ? 0 : ld + 1;
            }
            cmp = (cmp == 2) ? 0 : cmp + 1;
        }
        __syncthreads();  // stages free before next pass refill

        int quad = lane >> 2, ql = lane & 3;
        if (pass == 0) {
            #pragma unroll
            for (int mf = 0; mf < 2; ++mf)
                #pragma unroll
                for (int h = 0; h < 2; ++h) {
                    int li = wm * 32 + mf * 16 + quad + h * 8;
                    int tk = tokS[li];
                    #pragma unroll
                    for (int n8 = 0; n8 < 4; ++n8) {
                        int cc = col0 + wn * 32 + n8 * 8 + ql * 2;
                        const float2 b2 = *(const float2*)&g.baseG[(long)tk * kI + cc];
                        float g0 = b2.x + acc[mf][n8][h * 2 + 0];
                        float g1 = b2.y + acc[mf][n8][h * 2 + 1];
                        sg[mf][n8][h * 2 + 0] = g0 / (1.0f + expf(-g0));
                        sg[mf][n8][h * 2 + 1] = g1 / (1.0f + expf(-g1));
                    }
                }
        } else {
            unsigned short* Hh = g.Hh + (long)ez * kT * kI;
            unsigned short* Hl = g.Hl + (long)ez * kT * kI;
            #pragma unroll
            for (int mf = 0; mf < 2; ++mf)
                #pragma unroll
                for (int h = 0; h < 2; ++h) {
                    int li = wm * 32 + mf * 16 + quad + h * 8;
                    int r = row0 + li;
                    if (r >= M) continue;
                    int tk = tokS[li];
                    float w = wS[li];
                    #pragma unroll
                    for (int n8 = 0; n8 < 4; ++n8) {
                        int cc = col0 + wn * 32 + n8 * 8 + ql * 2;
                        const float2 b2 = *(const float2*)&g.baseU[(long)tk * kI + cc];
                        float u0 = b2.x + acc[mf][n8][h * 2 + 0];
                        float u1 = b2.y + acc[mf][n8][h * 2 + 1];
                        float h0f = sg[mf][n8][h * 2 + 0] * u0;
                        float h1f = sg[mf][n8][h * 2 + 1] * u1;
                        unsigned short h0, l0, h1, l1;
                        split_bf16(h0f, h0, l0);
                        split_bf16(h1f, h1, l1);
                        long o = (long)r * kI + cc;
                        *(ushort2*)&Hh[o] = make_ushort2(h0, h1);
                        *(ushort2*)&Hl[o] = make_ushort2(l0, l1);
                        red_v2(&g.hbar[(long)tk * kI + cc], w * h0f, w * h1f);
                    }
                }
        }
    }
}

// ---------------- host-side dispatch ----------------
static void launchG(const GArgs& a, dim3 grid) {
    switch (a.mode) {
        case 0: gemm_mma<0><<<grid, 256, GSMEM>>>(a); break;
        case 2: gemm_mma<2><<<grid, 256, GSMEM>>>(a); break;
        case 3: gemm_mma<3><<<grid, 256, GSMEM>>>(a); break;
        default: gemm_mma<5><<<grid, 256, GSMEM>>>(a); break;
    }
}

// ---------------- launch ----------------
extern "C" void kernel_launch(void* const* d_in, const int* in_sizes, int n_in,
                              void* d_out, int out_size) {
    const float* x  = (const float*)d_in[0];
    const float* wr = (const float*)d_in[1];
    const float* Wg = (const float*)d_in[2];
    const float* Wu = (const float*)d_in[3];
    const float* Wd = (const float*)d_in[4];
    const float* Ag = (const float*)d_in[5];
    const float* Bg = (const float*)d_in[6];
    const float* Au = (const float*)d_in[7];
    const float* Bu = (const float*)d_in[8];
    const float* Ad = (const float*)d_in[9];
    const float* Bd = (const float*)d_in[10];

    float* out = (float*)d_out;
    float* logits_out = out + (long)kT * kH;

    void* p;
#define SYM(var, name) cudaGetSymbolAddress(&p, name); auto* var = (unsigned short*)p;
    SYM(xs_hi, d_xs_hi) SYM(xs_lo, d_xs_lo)
    SYM(wgu_hi, d_wgu_hi) SYM(wgu_lo, d_wgu_lo)
    SYM(wd_hi, d_wd_hi) SYM(wd_lo, d_wd_lo)
    SYM(ag_hi, d_ag_hi) SYM(ag_lo, d_ag_lo)
    SYM(au_hi, d_au_hi) SYM(au_lo, d_au_lo)
    SYM(bg_hi, d_bg_hi) SYM(bg_lo, d_bg_lo)
    SYM(bu_hi, d_bu_hi) SYM(bu_lo, d_bu_lo)
    SYM(ad_hi, d_ad_hi) SYM(ad_lo, d_ad_lo)
    SYM(bd_hi, d_bd_hi) SYM(bd_lo, d_bd_lo)
    SYM(tgu_hi, d_tgu_hi) SYM(tgu_lo, d_tgu_lo)
    SYM(td_hi, d_td_hi) SYM(td_lo, d_td_lo)
    SYM(h_hi, d_h_hi)   SYM(h_lo, d_h_lo)
    SYM(hb_hi, d_hb_hi) SYM(hb_lo, d_hb_lo)
#undef SYM
    cudaGetSymbolAddress(&p, g_base_gu); float* base_gu = (float*)p;
    cudaGetSymbolAddress(&p, g_hbar);    float* hbar = (float*)p;
    cudaGetSymbolAddress(&p, g_combine); float* combine = (float*)p;
    cudaGetSymbolAddress(&p, g_lists);   int* lists = (int*)p;
    cudaGetSymbolAddress(&p, g_counts);  int* counts = (int*)p;

    cudaFuncSetAttribute(gemm_mma<0>, cudaFuncAttributeMaxDynamicSharedMemorySize, GSMEM);
    cudaFuncSetAttribute(gemm_mma<2>, cudaFuncAttributeMaxDynamicSharedMemorySize, GSMEM);
    cudaFuncSetAttribute(gemm_mma<3>, cudaFuncAttributeMaxDynamicSharedMemorySize, GSMEM);
    cudaFuncSetAttribute(gemm_mma<5>, cudaFuncAttributeMaxDynamicSharedMemorySize, GSMEM);
    cudaFuncSetAttribute(gemm_bc, cudaFuncAttributeMaxDynamicSharedMemorySize, BC_SMEM);

    auto mkargs = [&]() {
        GArgs a;
        a.A1h = a.A1l = nullptr; a.lda1 = 0;
        a.Bh = a.Bl = a.Bn2h = a.Bn2l = nullptr;
        a.ldb = 0; a.nBv = 0; a.nSplit = 1 << 30; a.nBn2v = 0;
        a.K = 0; a.C = nullptr; a.ldc = 0;
        a.M_static = kT; a.countBase = nullptr; a.listBase = nullptr; a.gatherA = 0;
        a.combine = nullptr;
        a.Ch = a.Cl = nullptr; a.mode = 0; a.useW = 0;
        a.eStrideA1 = a.eStrideB = a.eStrideBn2 = 0;
        a.eStrideC = 0;
        return a;
    };

    splitv_kernel<<<dim3(1, kT), 256>>>(x, kH, xs_hi, xs_lo, kH);
    splitv_kernel<<<dim3(1, kI), 256>>>(Wg, kH, wgu_hi, wgu_lo, kH);
    splitv_kernel<<<dim3(1, kI), 256>>>(Wu, kH, wgu_hi + (long)kI * kH, wgu_lo + (long)kI * kH, kH);
    init_kernel<<<2048, 256>>>(hbar);
    {
        GArgs a = mkargs();
        a.A1h = xs_hi; a.A1l = xs_lo; a.lda1 = kH;
        a.Bh = wgu_hi; a.Bl = wgu_lo; a.ldb = kH; a.nBv = kI;
        a.eStrideB = (long)kI * kH;
        a.K = kH; a.C = base_gu; a.ldc = kI; a.eStrideC = (long)kT * kI;
        a.mode = 0;
        launchG(a, dim3(8, 64, 2));
    }
    router_kernel<<<kT, 256>>>(x, wr, logits_out);

    splitv_kernel<<<dim3(1, kH), 256>>>(Wd, kI, wd_hi, wd_lo, kI);
    splitv_kernel<<<dim3(1, kE * kR), 256>>>(Ag, kH, ag_hi, ag_lo, kH);
    splitv_kernel<<<dim3(1, kE * kR), 256>>>(Au, kH, au_hi, au_lo, kH);
    splitv_kernel<<<dim3(1, kE * kI), 256>>>(Bg, kR, bg_hi, bg_lo, kRP);
    splitv_kernel<<<dim3(1, kE * kI), 256>>>(Bu, kR, bu_hi, bu_lo, kRP);
    splitv_kernel<<<dim3(1, kE * kR), 256>>>(Ad, kI, ad_hi, ad_lo, kI);
    splitv_kernel<<<dim3(1, kE * kH), 256>>>(Bd, kR, bd_hi, bd_lo, kRP);

    // phase A: tg|tu = gather(x) @ [Ag;Au]^T -> split  [n_e,1280], K=2048, z=16
    {
        GArgs a = mkargs();
        a.A1h = xs_hi; a.A1l = xs_lo; a.lda1 = kH;
        a.Bh = ag_hi; a.Bl = ag_lo; a.ldb = kH; a.nBv = kR;
        a.eStrideB = (long)kR * kH;
        a.Bn2h = au_hi; a.Bn2l = au_lo; a.nSplit = kRP; a.nBn2v = kR;
        a.eStrideBn2 = (long)kR * kH;
        a.K = kH; a.countBase = counts; a.listBase = lists; a.gatherA = 1;
        a.Ch = tgu_hi; a.Cl = tgu_lo; a.ldc = 2 * kRP;
        a.eStrideC = (long)kT * 2 * kRP; a.mode = 3;
        launchG(a, dim3(10, 64, kE));
    }
    // phase BC fused: h = silu(base_g + tg@Bg^T) * (base_u + tu@Bu^T), hbar += w*h
    {
        BCArgs b;
        b.Ah = tgu_hi; b.Al = tgu_lo;
        b.Bgh = bg_hi; b.Bgl = bg_lo;
        b.Buh = bu_hi; b.Bul = bu_lo;
        b.baseG = base_gu; b.baseU = base_gu + (long)kT * kI;
        b.combine = combine; b.hbar = hbar;
        b.Hh = h_hi; b.Hl = h_lo;
        b.counts = counts; b.lists = lists;
        gemm_bc<<<dim3(16, 64, kE), 256, BC_SMEM>>>(b);
    }
    // phase D: td = w * (h @ Ad^T) -> split  [n_e,640], K=1024, z=16
    {
        GArgs a = mkargs();
        a.A1h = h_hi; a.A1l = h_lo; a.lda1 = kI;
        a.eStrideA1 = (long)kT * kI;
        a.Bh = ad_hi; a.Bl = ad_lo; a.ldb = kI; a.nBv = kR;
        a.eStrideB = (long)kR * kI;
        a.K = kI; a.countBase = counts; a.listBase = lists;
        a.combine = combine; a.useW = 1;
        a.Ch = td_hi; a.Cl = td_lo; a.ldc = kRP; a.eStrideC = (long)kT * kRP;
        a.mode = 3;
        launchG(a, dim3(5, 64, kE));
    }
    // phase F first: out = hbar @ Wd^T  (direct write, no init needed)
    splitv_kernel<<<dim3(1, kT), 256>>>(hbar, kI, hb_hi, hb_lo, kI);
    {
        GArgs a = mkargs();
        a.A1h = hb_hi; a.A1l = hb_lo; a.lda1 = kI;
        a.Bh = wd_hi; a.Bl = wd_lo; a.ldb = kI; a.nBv = kH;
        a.K = kI; a.C = out; a.ldc = kH; a.mode = 0;
        launchG(a, dim3(16, 64, 1));
    }
    // phase E: out[tok] += td @ Bd^T  (weight prefolded)  [n_e,2048], K=640
    {
        GArgs a = mkargs();
        a.A1h = td_hi; a.A1l = td_lo; a.lda1 = kRP;
        a.eStrideA1 = (long)kT * kRP;
        a.Bh = bd_hi; a.Bl = bd_lo; a.ldb = kRP; a.nBv = kH;
        a.eStrideB = (long)kH * kRP;
        a.K = kRP; a.countBase = counts; a.listBase = lists;
        a.C = out; a.ldc = kH; a.eStrideC = 0; a.mode = 2;
        launchG(a, dim3(16, 64, kE));
    }

    (void)in_sizes; (void)n_in; (void)out_size;
}

// round 16
// speedup vs baseline: 1.0056x; 1.0056x over previous
#include <cuda_runtime.h>
#include <cuda_bf16.h>
#include <cstdint>
#include <math.h>

constexpr int kH = 2048, kI = 1024, kE = 16, kTopK = 8, kR = 602, kT = 8192;
constexpr int kRP = 640;

// ---------------- device scratch ----------------
__device__ __align__(16) unsigned short d_xs_hi[kT * kH];
__device__ __align__(16) unsigned short d_xs_lo[kT * kH];
__device__ __align__(16) unsigned short d_wgu_hi[2 * kI * kH];
__device__ __align__(16) unsigned short d_wgu_lo[2 * kI * kH];
__device__ __align__(16) unsigned short d_wd_hi[kH * kI];
__device__ __align__(16) unsigned short d_wd_lo[kH * kI];
__device__ __align__(16) unsigned short d_ag_hi[kE * kR * kH];
__device__ __align__(16) unsigned short d_ag_lo[kE * kR * kH];
__device__ __align__(16) unsigned short d_au_hi[kE * kR * kH];
__device__ __align__(16) unsigned short d_au_lo[kE * kR * kH];
__device__ __align__(16) unsigned short d_bg_hi[kE * kI * kRP];
__device__ __align__(16) unsigned short d_bg_lo[kE * kI * kRP];
__device__ __align__(16) unsigned short d_bu_hi[kE * kI * kRP];
__device__ __align__(16) unsigned short d_bu_lo[kE * kI * kRP];
__device__ __align__(16) unsigned short d_ad_hi[kE * kR * kI];
__device__ __align__(16) unsigned short d_ad_lo[kE * kR * kI];
__device__ __align__(16) unsigned short d_bd_hi[kE * kH * kRP];
__device__ __align__(16) unsigned short d_bd_lo[kE * kH * kRP];
__device__ __align__(16) unsigned short d_tgu_hi[kE * kT * 2 * kRP];
__device__ __align__(16) unsigned short d_tgu_lo[kE * kT * 2 * kRP];
__device__ __align__(16) unsigned short d_td_hi[kE * kT * kRP];
__device__ __align__(16) unsigned short d_td_lo[kE * kT * kRP];
__device__ __align__(16) unsigned short d_h_hi[kE * kT * kI];
__device__ __align__(16) unsigned short d_h_lo[kE * kT * kI];
__device__ __align__(16) unsigned short d_hb_hi[kT * kI];
__device__ __align__(16) unsigned short d_hb_lo[kT * kI];
__device__ float g_base_gu[2 * kT * kI];
__device__ float g_gbuf[kE * kT * kI];
__device__ float g_hbar[kT * kI];
__device__ float g_combine[kT * kE];
__device__ int   g_lists[kE * kT];
__device__ int   g_counts[kE];

// ---------------- helpers ----------------
__device__ __forceinline__ uint32_t smem_u32(const void* p) {
    uint32_t a;
    asm("{ .reg .u64 t; cvta.to.shared.u64 t, %1; cvt.u32.u64 %0, t; }"
        : "=r"(a) : "l"(p));
    return a;
}
__device__ __forceinline__ void split_bf16(float v, unsigned short& h, unsigned short& l) {
    __nv_bfloat16 bh = __float2bfloat16(v);
    float r = v - __bfloat162float(bh);
    __nv_bfloat16 bl = __float2bfloat16(r);
    h = __bfloat16_as_ushort(bh);
    l = __bfloat16_as_ushort(bl);
}
__device__ __forceinline__ void red_v2(float* ptr, float a, float b) {
    asm volatile("red.global.add.v2.f32 [%0], {%1, %2};"
                 :: "l"(ptr), "f"(a), "f"(b) : "memory");
}

#define LDM4(r, a)                                                            \
    asm volatile("ldmatrix.sync.aligned.m8n8.x4.shared.b16 {%0,%1,%2,%3}, [%4];" \
                 : "=r"((r)[0]), "=r"((r)[1]), "=r"((r)[2]), "=r"((r)[3])     \
                 : "r"(a))

#define MMA(c, a, b0, b1)                                                     \
    asm volatile("mma.sync.aligned.m16n8k16.row.col.f32.bf16.bf16.f32 "       \
                 "{%0,%1,%2,%3},{%4,%5,%6,%7},{%8,%9},{%0,%1,%2,%3};"         \
                 : "+f"((c)[0]), "+f"((c)[1]), "+f"((c)[2]), "+f"((c)[3])     \
                 : "r"((a)[0]), "r"((a)[1]), "r"((a)[2]), "r"((a)[3]),        \
                   "r"(b0), "r"(b1))

#define MMA6(accA, accB, ah, al, bh, bl)                                      \
    do {                                                                      \
        MMA(accA, ah, (bh)[0], (bh)[2]);                                      \
        MMA(accB, ah, (bh)[1], (bh)[3]);                                      \
        MMA(accA, ah, (bl)[0], (bl)[2]);                                      \
        MMA(accB, ah, (bl)[1], (bl)[3]);                                      \
        MMA(accA, al, (bh)[0], (bh)[2]);                                      \
        MMA(accB, al, (bh)[1], (bh)[3]);                                      \
    } while (0)

__device__ __forceinline__ void cpa16(uint32_t dst, const void* src, int sz) {
    asm volatile("cp.async.cg.shared.global [%0], [%1], 16, %2;"
                 :: "r"(dst), "l"(src), "r"(sz));
}

__device__ __forceinline__ uint32_t swz(int row, int chunk) {
    return (uint32_t)(row * 64 + ((chunk ^ ((row >> 1) & 3)) << 4));
}

// ---------------- init: hbar + counts only (out written directly by phase F)
__global__ void init_kernel(float* __restrict__ hbar) {
    long idx = (long)blockIdx.x * blockDim.x + threadIdx.x;
    long stride = (long)gridDim.x * blockDim.x;
    long totalH = (long)(kT * kI) / 4;
    float4 z = make_float4(0.f, 0.f, 0.f, 0.f);
    float4* h4 = (float4*)hbar;
    for (long i = idx; i < totalH; i += stride) h4[i] = z;
    if (idx < kE) g_counts[idx] = 0;
}

// ---------------- router ----------------
__global__ void router_kernel(const float* __restrict__ x,
                              const float* __restrict__ wr,
                              float* __restrict__ logits_out) {
    int t = blockIdx.x;
    __shared__ float xs[kH];
    __shared__ float lg[kE];
    int tid = threadIdx.x;
    for (int i = tid; i < kH; i += 256) xs[i] = x[(long)t * kH + i];
    __syncthreads();
    int w = tid >> 5, lane = tid & 31;
    #pragma unroll
    for (int eo = 0; eo < 2; eo++) {
        int e = w * 2 + eo;
        const float* wre = wr + (long)e * kH;
        float s = 0.0f;
        for (int i = lane; i < kH; i += 32) s += xs[i] * wre[i];
        #pragma unroll
        for (int o = 16; o; o >>= 1) s += __shfl_xor_sync(0xffffffff, s, o);
        if (lane == 0) lg[e] = s;
    }
    __syncthreads();
    if (tid == 0) {
        float mx = lg[0];
        for (int e = 1; e < kE; e++) mx = fmaxf(mx, lg[e]);
        float p[kE]; float sum = 0.0f;
        for (int e = 0; e < kE; e++) { p[e] = expf(lg[e] - mx); sum += p[e]; }
        float inv = 1.0f / sum;
        for (int e = 0; e < kE; e++) p[e] *= inv;
        bool used[kE];
        for (int e = 0; e < kE; e++) used[e] = false;
        int sel[kTopK]; float tsum = 0.0f;
        for (int k = 0; k < kTopK; k++) {
            int bi = -1; float bv = -1.0f;
            for (int e = 0; e < kE; e++)
                if (!used[e] && p[e] > bv) { bv = p[e]; bi = e; }
            used[bi] = true; sel[k] = bi; tsum += bv;
        }
        float itn = 1.0f / tsum;
        for (int e = 0; e < kE; e++)
            g_combine[t * kE + e] = used[e] ? p[e] * itn : 0.0f;
        for (int k = 0; k < kTopK; k++) {
            int e = sel[k];
            int pos = atomicAdd(&g_counts[e], 1);
            g_lists[e * kT + pos] = t;
        }
    }
    if (tid < kE) logits_out[t * kE + tid] = lg[tid];
}

// ---------------- vectorized split ----------------
__global__ void splitv_kernel(const float* __restrict__ src, int srcLd,
                              unsigned short* __restrict__ hi,
                              unsigned short* __restrict__ lo, int dstLd) {
    long row = blockIdx.y;
    int col = (blockIdx.x * 256 + threadIdx.x) * 8;
    if (col >= dstLd) return;
    const float* s = src + row * srcLd;
    unsigned short h[8], l[8];
    #pragma unroll
    for (int j = 0; j < 8; ++j) {
        float v = (col + j < srcLd) ? __ldg(s + col + j) : 0.0f;
        split_bf16(v, h[j], l[j]);
    }
    long o = row * dstLd + col;
    *(uint4*)(hi + o) = *(const uint4*)h;
    *(uint4*)(lo + o) = *(const uint4*)l;
}

// ---------------- mma.sync bf16 GEMM, 3-term split, grouped over z ----------
// CTA 128x128, 8 warps (4m x 2n) of 32x64. Swizzled 64B rows, 3-stage
// cp.async, one barrier per k-tile, 2 CTAs/SM. MODE templated.
// 0: C=acc ; 1: C=base[tok]+acc ; 2: red.v2(C[tok], acc) ;
// 3: split->Ch/Cl (×w if useW) ;
// 4: h=silu(gmul)*(base[tok]+acc) -> split, red.v2(hbar[tok], w*h)
struct GArgs {
    const unsigned short *A1h, *A1l; int lda1;
    const unsigned short *Bh, *Bl;   int ldb;  int nBv;
    const unsigned short *Bn2h, *Bn2l; int nSplit; int nBn2v;
    int K;
    float* C; int ldc;
    int M_static; const int* countBase; const int* listBase; int gatherA;
    const float* base; int ldbase;
    const float* combine;
    const float* gmul;
    float* hbar;
    unsigned short *Ch, *Cl;
    int mode;
    int useW;
    long eStrideA1, eStrideB, eStrideBn2;
    long eStrideC, eStrideG;
};

constexpr int STAGE_B = 32768;
constexpr int PL = 8192;
constexpr int GSMEM = 3072 + 3 * STAGE_B;  // 101376 -> 2 CTAs/SM

template <int MODE>
__global__ __launch_bounds__(256, 2) void gemm_mma(GArgs g) {
    int ez = blockIdx.z;
    int M = g.countBase ? g.countBase[ez] : g.M_static;
    int row0 = blockIdx.y * 128;
    if (row0 >= M) return;
    int col0 = blockIdx.x * 128;

    const unsigned short* A1h = g.A1h + (long)ez * g.eStrideA1;
    const unsigned short* A1l = g.A1l + (long)ez * g.eStrideA1;
    const unsigned short* Bh  = g.Bh + (long)ez * g.eStrideB;
    const unsigned short* Bl  = g.Bl + (long)ez * g.eStrideB;
    float* C = g.C ? g.C + (long)ez * g.eStrideC : nullptr;
    unsigned short* Ch = g.Ch ? g.Ch + (long)ez * g.eStrideC : nullptr;
    unsigned short* Cl = g.Cl ? g.Cl + (long)ez * g.eStrideC : nullptr;
    const float* gmul = g.gmul ? g.gmul + (long)ez * g.eStrideG : nullptr;
    const int* list = g.listBase ? g.listBase + (long)ez * kT : nullptr;

    extern __shared__ char sm[];
    int*   arow = (int*)sm;
    int*   tokS = (int*)(sm + 1024);
    float* wS   = (float*)(sm + 2048);
    uint32_t stages_u = smem_u32(sm + 3072);

    int tid = threadIdx.x;
    int lane = tid & 31, wid = tid >> 5;
    int wm = wid & 3, wn = wid >> 2;

    if (tid < 128) {
        int i = tid;
        int r = row0 + i;
        int rr = (r < M) ? r : (M - 1);
        int tk = list ? list[rr] : rr;
        tokS[i] = tk;
        arow[i] = g.gatherA ? tk : rr;
        wS[i] = (MODE == 4 || (MODE == 3 && g.useW))
                    ? g.combine[tk * kE + ez] : 1.0f;
    }
    __syncthreads();

    int c8 = tid & 3;
    int rA0 = tid >> 2, rA1 = (tid + 256) >> 2;
    const unsigned short* aH0 = A1h + (long)arow[rA0] * g.lda1 + c8 * 8;
    const unsigned short* aL0 = A1l + (long)arow[rA0] * g.lda1 + c8 * 8;
    const unsigned short* aH1 = A1h + (long)arow[rA1] * g.lda1 + c8 * 8;
    const unsigned short* aL1 = A1l + (long)arow[rA1] * g.lda1 + c8 * 8;
    uint32_t aD0 = swz(rA0, c8), aD1 = swz(rA1, c8);

    const unsigned short *bH0, *bL0, *bH1, *bL1;
    int v0, v1;
    {
        int gn = col0 + rA0;
        int rr; const unsigned short *ph, *pl;
        if (gn >= g.nSplit) { ph = g.Bn2h + (long)ez * g.eStrideBn2; pl = g.Bn2l + (long)ez * g.eStrideBn2; rr = gn - g.nSplit; v0 = (rr < g.nBn2v) ? 16 : 0; }
        else                { ph = Bh; pl = Bl; rr = gn; v0 = (gn < g.nBv) ? 16 : 0; }
        if (!v0) rr = 0;
        bH0 = ph + (long)rr * g.ldb + c8 * 8;
        bL0 = pl + (long)rr * g.ldb + c8 * 8;
        gn = col0 + rA1;
        if (gn >= g.nSplit) { ph = g.Bn2h + (long)ez * g.eStrideBn2; pl = g.Bn2l + (long)ez * g.eStrideBn2; rr = gn - g.nSplit; v1 = (rr < g.nBn2v) ? 16 : 0; }
        else                { ph = Bh; pl = Bl; rr = gn; v1 = (gn < g.nBv) ? 16 : 0; }
        if (!v1) rr = 0;
        bH1 = ph + (long)rr * g.ldb + c8 * 8;
        bL1 = pl + (long)rr * g.ldb + c8 * 8;
    }
    uint32_t bD0 = swz(rA0, c8), bD1 = swz(rA1, c8);

    uint32_t aAddr[2][2], bAddr[4][2];
    {
        int ch0 = lane >> 4;
        #pragma unroll
        for (int mf = 0; mf < 2; ++mf) {
            int row = wm * 32 + mf * 16 + (lane & 15);
            #pragma unroll
            for (int k16 = 0; k16 < 2; ++k16)
                aAddr[mf][k16] = swz(row, ch0 + k16 * 2);
        }
        #pragma unroll
        for (int n16 = 0; n16 < 4; ++n16) {
            int row = wn * 64 + n16 * 16 + (lane & 15);
            #pragma unroll
            for (int k16 = 0; k16 < 2; ++k16)
                bAddr[n16][k16] = swz(row, ch0 + k16 * 2);
        }
    }

    float acc[2][8][4];
    #pragma unroll
    for (int a = 0; a < 2; a++)
        #pragma unroll
        for (int b = 0; b < 8; b++)
            #pragma unroll
            for (int c = 0; c < 4; c++) acc[a][b][c] = 0.0f;

    int nk = g.K >> 5;

    auto load_tile = [&](int stg) {
        uint32_t st = stages_u + stg * STAGE_B;
        cpa16(st + aD0, aH0, 16);
        cpa16(st + PL + aD0, aL0, 16);
        cpa16(st + aD1, aH1, 16);
        cpa16(st + PL + aD1, aL1, 16);
        cpa16(st + 2 * PL + bD0, bH0, v0);
        cpa16(st + 3 * PL + bD0, bL0, v0);
        cpa16(st + 2 * PL + bD1, bH1, v1);
        cpa16(st + 3 * PL + bD1, bL1, v1);
        asm volatile("cp.async.commit_group;");
        aH0 += 32; aL0 += 32; aH1 += 32; aL1 += 32;
        bH0 += 32; bL0 += 32; bH1 += 32; bL1 += 32;
    };

    load_tile(0);
    load_tile(1);
    int cmp = 0, ld = 2;
    for (int k = 0; k < nk; ++k) {
        if (k == nk - 1) asm volatile("cp.async.wait_group 0;");
        else             asm volatile("cp.async.wait_group 1;");
        __syncthreads();
        uint32_t sb = stages_u + cmp * STAGE_B;
        #pragma unroll
        for (int k16 = 0; k16 < 2; ++k16) {
            uint32_t ah[2][4], al[2][4];
            #pragma unroll
            for (int mf = 0; mf < 2; ++mf) {
                LDM4(ah[mf], sb + aAddr[mf][k16]);
                LDM4(al[mf], sb + PL + aAddr[mf][k16]);
            }
            #pragma unroll
            for (int n16 = 0; n16 < 4; ++n16) {
                uint32_t bh[4], bl[4];
                LDM4(bh, sb + 2 * PL + bAddr[n16][k16]);
                LDM4(bl, sb + 3 * PL + bAddr[n16][k16]);
                #pragma unroll
                for (int mf = 0; mf < 2; ++mf)
                    MMA6(acc[mf][n16 * 2 + 0], acc[mf][n16 * 2 + 1],
                         ah[mf], al[mf], bh, bl);
            }
        }
        if (k + 2 < nk) {
            load_tile(ld);
            ld = (ld == 2) ? 0 : ld + 1;
        }
        cmp = (cmp == 2) ? 0 : cmp + 1;
    }

    int quad = lane >> 2, ql = lane & 3;
    #pragma unroll
    for (int mf = 0; mf < 2; ++mf) {
        #pragma unroll
        for (int h = 0; h < 2; ++h) {
            int li = wm * 32 + mf * 16 + quad + h * 8;
            int r = row0 + li;
            if (r >= M) continue;
            int tk = tokS[li];
            float w = wS[li];
            #pragma unroll
            for (int n8 = 0; n8 < 8; ++n8) {
                int cc = col0 + wn * 64 + n8 * 8 + ql * 2;
                float v0f = acc[mf][n8][h * 2 + 0];
                float v1f = acc[mf][n8][h * 2 + 1];
                if (MODE == 0) {
                    *(float2*)&C[(long)r * g.ldc + cc] = make_float2(v0f, v1f);
                } else if (MODE == 1) {
                    const float2 b2 = *(const float2*)&g.base[(long)tk * g.ldbase + cc];
                    *(float2*)&C[(long)r * g.ldc + cc] = make_float2(b2.x + v0f, b2.y + v1f);
                } else if (MODE == 2) {
                    red_v2(&C[(long)tk * g.ldc + cc], v0f, v1f);
                } else if (MODE == 3) {
                    unsigned short h0, l0, h1, l1;
                    split_bf16(w * v0f, h0, l0);
                    split_bf16(w * v1f, h1, l1);
                    long o = (long)r * g.ldc + cc;
                    *(ushort2*)&Ch[o] = make_ushort2(h0, h1);
                    *(ushort2*)&Cl[o] = make_ushort2(l0, l1);
                } else if (MODE == 4) {
                    const float2 b2 = *(const float2*)&g.base[(long)tk * g.ldbase + cc];
                    float u0 = b2.x + v0f, u1 = b2.y + v1f;
                    const float2 g2 = *(const float2*)&gmul[(long)r * g.ldc + cc];
                    float h0f = g2.x / (1.0f + expf(-g2.x)) * u0;
                    float h1f = g2.y / (1.0f + expf(-g2.y)) * u1;
                    unsigned short h0, l0, h1, l1;
                    split_bf16(h0f, h0, l0);
                    split_bf16(h1f, h1, l1);
                    long o = (long)r * g.ldc + cc;
                    *(ushort2*)&Ch[o] = make_ushort2(h0, h1);
                    *(ushort2*)&Cl[o] = make_ushort2(l0, l1);
                    red_v2(&g.hbar[(long)tk * g.ldc + cc], w * h0f, w * h1f);
                }
            }
        }
    }
}

// ---------------- host-side dispatch ----------------
static void launchG(const GArgs& a, dim3 grid) {
    switch (a.mode) {
        case 0: gemm_mma<0><<<grid, 256, GSMEM>>>(a); break;
        case 1: gemm_mma<1><<<grid, 256, GSMEM>>>(a); break;
        case 2: gemm_mma<2><<<grid, 256, GSMEM>>>(a); break;
        case 3: gemm_mma<3><<<grid, 256, GSMEM>>>(a); break;
        default: gemm_mma<4><<<grid, 256, GSMEM>>>(a); break;
    }
}

// ---------------- launch ----------------
extern "C" void kernel_launch(void* const* d_in, const int* in_sizes, int n_in,
                              void* d_out, int out_size) {
    const float* x  = (const float*)d_in[0];
    const float* wr = (const float*)d_in[1];
    const float* Wg = (const float*)d_in[2];
    const float* Wu = (const float*)d_in[3];
    const float* Wd = (const float*)d_in[4];
    const float* Ag = (const float*)d_in[5];
    const float* Bg = (const float*)d_in[6];
    const float* Au = (const float*)d_in[7];
    const float* Bu = (const float*)d_in[8];
    const float* Ad = (const float*)d_in[9];
    const float* Bd = (const float*)d_in[10];

    float* out = (float*)d_out;
    float* logits_out = out + (long)kT * kH;

    void* p;
#define SYM(var, name) cudaGetSymbolAddress(&p, name); auto* var = (unsigned short*)p;
    SYM(xs_hi, d_xs_hi) SYM(xs_lo, d_xs_lo)
    SYM(wgu_hi, d_wgu_hi) SYM(wgu_lo, d_wgu_lo)
    SYM(wd_hi, d_wd_hi) SYM(wd_lo, d_wd_lo)
    SYM(ag_hi, d_ag_hi) SYM(ag_lo, d_ag_lo)
    SYM(au_hi, d_au_hi) SYM(au_lo, d_au_lo)
    SYM(bg_hi, d_bg_hi) SYM(bg_lo, d_bg_lo)
    SYM(bu_hi, d_bu_hi) SYM(bu_lo, d_bu_lo)
    SYM(ad_hi, d_ad_hi) SYM(ad_lo, d_ad_lo)
    SYM(bd_hi, d_bd_hi) SYM(bd_lo, d_bd_lo)
    SYM(tgu_hi, d_tgu_hi) SYM(tgu_lo, d_tgu_lo)
    SYM(td_hi, d_td_hi) SYM(td_lo, d_td_lo)
    SYM(h_hi, d_h_hi)   SYM(h_lo, d_h_lo)
    SYM(hb_hi, d_hb_hi) SYM(hb_lo, d_hb_lo)
#undef SYM
    cudaGetSymbolAddress(&p, g_base_gu); float* base_gu = (float*)p;
    cudaGetSymbolAddress(&p, g_gbuf);    float* gb = (float*)p;
    cudaGetSymbolAddress(&p, g_hbar);    float* hbar = (float*)p;
    cudaGetSymbolAddress(&p, g_combine); float* combine = (float*)p;
    cudaGetSymbolAddress(&p, g_lists);   int* lists = (int*)p;
    cudaGetSymbolAddress(&p, g_counts);  int* counts = (int*)p;

    cudaFuncSetAttribute(gemm_mma<0>, cudaFuncAttributeMaxDynamicSharedMemorySize, GSMEM);
    cudaFuncSetAttribute(gemm_mma<1>, cudaFuncAttributeMaxDynamicSharedMemorySize, GSMEM);
    cudaFuncSetAttribute(gemm_mma<2>, cudaFuncAttributeMaxDynamicSharedMemorySize, GSMEM);
    cudaFuncSetAttribute(gemm_mma<3>, cudaFuncAttributeMaxDynamicSharedMemorySize, GSMEM);
    cudaFuncSetAttribute(gemm_mma<4>, cudaFuncAttributeMaxDynamicSharedMemorySize, GSMEM);

    auto mkargs = [&]() {
        GArgs a;
        a.A1h = a.A1l = nullptr; a.lda1 = 0;
        a.Bh = a.Bl = a.Bn2h = a.Bn2l = nullptr;
        a.ldb = 0; a.nBv = 0; a.nSplit = 1 << 30; a.nBn2v = 0;
        a.K = 0; a.C = nullptr; a.ldc = 0;
        a.M_static = kT; a.countBase = nullptr; a.listBase = nullptr; a.gatherA = 0;
        a.base = nullptr; a.ldbase = 0; a.combine = nullptr;
        a.gmul = nullptr; a.hbar = nullptr; a.Ch = a.Cl = nullptr; a.mode = 0;
        a.useW = 0;
        a.eStrideA1 = a.eStrideB = a.eStrideBn2 = 0;
        a.eStrideC = a.eStrideG = 0;
        return a;
    };

    splitv_kernel<<<dim3(1, kT), 256>>>(x, kH, xs_hi, xs_lo, kH);
    splitv_kernel<<<dim3(1, kI), 256>>>(Wg, kH, wgu_hi, wgu_lo, kH);
    splitv_kernel<<<dim3(1, kI), 256>>>(Wu, kH, wgu_hi + (long)kI * kH, wgu_lo + (long)kI * kH, kH);
    init_kernel<<<2048, 256>>>(hbar);
    {
        GArgs a = mkargs();
        a.A1h = xs_hi; a.A1l = xs_lo; a.lda1 = kH;
        a.Bh = wgu_hi; a.Bl = wgu_lo; a.ldb = kH; a.nBv = kI;
        a.eStrideB = (long)kI * kH;
        a.K = kH; a.C = base_gu; a.ldc = kI; a.eStrideC = (long)kT * kI;
        a.mode = 0;
        launchG(a, dim3(8, 64, 2));
    }
    router_kernel<<<kT, 256>>>(x, wr, logits_out);

    splitv_kernel<<<dim3(1, kH), 256>>>(Wd, kI, wd_hi, wd_lo, kI);
    splitv_kernel<<<dim3(1, kE * kR), 256>>>(Ag, kH, ag_hi, ag_lo, kH);
    splitv_kernel<<<dim3(1, kE * kR), 256>>>(Au, kH, au_hi, au_lo, kH);
    splitv_kernel<<<dim3(1, kE * kI), 256>>>(Bg, kR, bg_hi, bg_lo, kRP);
    splitv_kernel<<<dim3(1, kE * kI), 256>>>(Bu, kR, bu_hi, bu_lo, kRP);
    splitv_kernel<<<dim3(1, kE * kR), 256>>>(Ad, kI, ad_hi, ad_lo, kI);
    splitv_kernel<<<dim3(1, kE * kH), 256>>>(Bd, kR, bd_hi, bd_lo, kRP);

    // phase A: tg|tu = gather(x) @ [Ag;Au]^T -> split  [n_e,1280], K=2048, z=16
    {
        GArgs a = mkargs();
        a.A1h = xs_hi; a.A1l = xs_lo; a.lda1 = kH;
        a.Bh = ag_hi; a.Bl = ag_lo; a.ldb = kH; a.nBv = kR;
        a.eStrideB = (long)kR * kH;
        a.Bn2h = au_hi; a.Bn2l = au_lo; a.nSplit = kRP; a.nBn2v = kR;
        a.eStrideBn2 = (long)kR * kH;
        a.K = kH; a.countBase = counts; a.listBase = lists; a.gatherA = 1;
        a.Ch = tgu_hi; a.Cl = tgu_lo; a.ldc = 2 * kRP;
        a.eStrideC = (long)kT * 2 * kRP; a.mode = 3;
        launchG(a, dim3(10, 64, kE));
    }
    // phase B: g = base_g[tok] + tg @ Bg^T -> gbuf  [n_e,1024], K=640, z=16
    {
        GArgs a = mkargs();
        a.A1h = tgu_hi; a.A1l = tgu_lo; a.lda1 = 2 * kRP;
        a.eStrideA1 = (long)kT * 2 * kRP;
        a.Bh = bg_hi; a.Bl = bg_lo; a.ldb = kRP; a.nBv = kI;
        a.eStrideB = (long)kI * kRP;
        a.K = kRP; a.countBase = counts; a.listBase = lists;
        a.base = base_gu; a.ldbase = kI;
        a.C = gb; a.ldc = kI; a.eStrideC = (long)kT * kI; a.mode = 1;
        launchG(a, dim3(8, 64, kE));
    }
    // phase C: h = silu(g)*(base_u[tok] + tu @ Bu^T) -> split, hbar += w*h  z=16
    {
        GArgs a = mkargs();
        a.A1h = tgu_hi + kRP; a.A1l = tgu_lo + kRP; a.lda1 = 2 * kRP;
        a.eStrideA1 = (long)kT * 2 * kRP;
        a.Bh = bu_hi; a.Bl = bu_lo; a.ldb = kRP; a.nBv = kI;
        a.eStrideB = (long)kI * kRP;
        a.K = kRP; a.countBase = counts; a.listBase = lists;
        a.base = base_gu + (long)kT * kI; a.ldbase = kI;
        a.gmul = gb; a.eStrideG = (long)kT * kI;
        a.combine = combine; a.hbar = hbar;
        a.Ch = h_hi; a.Cl = h_lo; a.ldc = kI; a.eStrideC = (long)kT * kI;
        a.mode = 4;
        launchG(a, dim3(8, 64, kE));
    }
    // phase D: td = w * (h @ Ad^T) -> split  [n_e,640], K=1024, z=16
    {
        GArgs a = mkargs();
        a.A1h = h_hi; a.A1l = h_lo; a.lda1 = kI;
        a.eStrideA1 = (long)kT * kI;
        a.Bh = ad_hi; a.Bl = ad_lo; a.ldb = kI; a.nBv = kR;
        a.eStrideB = (long)kR * kI;
        a.K = kI; a.countBase = counts; a.listBase = lists;
        a.combine = combine; a.useW = 1;
        a.Ch = td_hi; a.Cl = td_lo; a.ldc = kRP; a.eStrideC = (long)kT * kRP;
        a.mode = 3;
        launchG(a, dim3(5, 64, kE));
    }
    // phase F FIRST: out = hbar @ Wd^T  (direct write, no init of out needed)
    splitv_kernel<<<dim3(1, kT), 256>>>(hbar, kI, hb_hi, hb_lo, kI);
    {
        GArgs a = mkargs();
        a.A1h = hb_hi; a.A1l = hb_lo; a.lda1 = kI;
        a.Bh = wd_hi; a.Bl = wd_lo; a.ldb = kI; a.nBv = kH;
        a.K = kI; a.C = out; a.ldc = kH; a.mode = 0;
        launchG(a, dim3(16, 64, 1));
    }
    // phase E: out[tok] += td @ Bd^T  (weight prefolded)  [n_e,2048], K=640
    {
        GArgs a = mkargs();
        a.A1h = td_hi; a.A1l = td_lo; a.lda1 = kRP;
        a.eStrideA1 = (long)kT * kRP;
        a.Bh = bd_hi; a.Bl = bd_lo; a.ldb = kRP; a.nBv = kH;
        a.eStrideB = (long)kH * kRP;
        a.K = kRP; a.countBase = counts; a.listBase = lists;
        a.C = out; a.ldc = kH; a.eStrideC = 0; a.mode = 2;
        launchG(a, dim3(16, 64, kE));
    }

    (void)in_sizes; (void)n_in; (void)out_size;
}